// round 4
// baseline (speedup 1.0000x reference)
#include <cuda_runtime.h>
#include <cuda_bf16.h>
#include <math.h>

#define H 512
#define W 512
#define NPIX (H * W)
#define NWORDS 16            // 512 rows / 32 bits

// Scratch (allocation-free rule: __device__ globals)
// d_pack[q*512 + c] = (wordA, wordB): bit j of wordA = surface-of-pred at
// (row = q*32+j, col = c); wordB likewise for gt. Coalesced in c.
__device__ uint2 d_pack[NWORDS * W];
__device__ float d_rowNum[H];
__device__ float d_rowDen[H];
__device__ unsigned int d_cnt;   // zero-init; atomicInc wraps -> self-resetting

// ---------------------------------------------------------------------------
// Kernel 1: binarize + erode + surface masks, bit-transposed column packing.
// Block = 32x32 tile. Surface bytes -> padded shared -> ballot transpose.
// ---------------------------------------------------------------------------
__global__ void k_pack(const float* __restrict__ pred, const float* __restrict__ gt) {
    __shared__ unsigned char sbA[32 * 33];
    __shared__ unsigned char sbB[32 * 33];

    const int tx = threadIdx.x;          // column within tile (lane)
    const int ty = threadIdx.y;          // row within tile (warp id)
    const int c = blockIdx.x * 32 + tx;
    const int r = blockIdx.y * 32 + ty;
    const int idx = r * W + c;

    {
        bool ctr = pred[idx] != 0.0f;
        bool up = (r > 0)     && (pred[idx - W] != 0.0f);
        bool dn = (r < H - 1) && (pred[idx + W] != 0.0f);
        bool lt = (c > 0)     && (pred[idx - 1] != 0.0f);
        bool rt = (c < W - 1) && (pred[idx + 1] != 0.0f);
        sbA[ty * 33 + tx] = (unsigned char)(ctr && !(up && dn && lt && rt));
    }
    {
        bool ctr = gt[idx] != 0.0f;
        bool up = (r > 0)     && (gt[idx - W] != 0.0f);
        bool dn = (r < H - 1) && (gt[idx + W] != 0.0f);
        bool lt = (c > 0)     && (gt[idx - 1] != 0.0f);
        bool rt = (c < W - 1) && (gt[idx + 1] != 0.0f);
        sbB[ty * 33 + tx] = (unsigned char)(ctr && !(up && dn && lt && rt));
    }
    __syncthreads();

    // Transpose: warp ty handles tile-column ty; lane tx supplies tile-row tx.
    const int wcol = ty;
    const int lrow = tx;
    unsigned wa = __ballot_sync(0xFFFFFFFFu, sbA[lrow * 33 + wcol] != 0);
    unsigned wb = __ballot_sync(0xFFFFFFFFu, sbB[lrow * 33 + wcol] != 0);
    if (lrow == 0) {
        d_pack[blockIdx.y * W + blockIdx.x * 32 + wcol] = make_uint2(wa, wb);
    }
}

// ---------------------------------------------------------------------------
// Exact vertical squared distance from (r, c) to nearest set bit in the
// packed column. wcur = word q of this column; col points at d_pack[c]
// (stride W per word). compB selects the .y component.
// ---------------------------------------------------------------------------
__device__ __forceinline__ float vdist2_bits(unsigned wcur, int q, int bit,
                                             const uint2* __restrict__ col,
                                             bool compB) {
    // nearest set bit at row <= r (bits 0..bit of wcur, then lower words)
    int du;
    unsigned upm = wcur & (0xFFFFFFFFu >> (31 - bit));
    if (upm) {
        du = bit - (31 - __clz(upm));
    } else {
        du = 1 << 20;
        for (int s = 1; s <= q; ++s) {
            uint2 v = col[(q - s) * W];
            unsigned x = compB ? v.y : v.x;
            if (x) { du = bit + s * 32 - (31 - __clz(x)); break; }
        }
    }
    // nearest set bit at row >= r (bits bit..31 of wcur, then higher words)
    int dd;
    unsigned dnm = wcur >> bit;
    if (dnm) {
        dd = __ffs(dnm) - 1;
    } else {
        dd = 1 << 20;
        for (int s = 1; q + s < NWORDS; ++s) {
            uint2 v = col[(q + s) * W];
            unsigned x = compB ? v.y : v.x;
            if (x) { dd = (32 - bit) + (s - 1) * 32 + (__ffs(x) - 1); break; }
        }
    }
    int dmin = min(du, dd);
    if (dmin >= (1 << 20)) return 1e12f;   // empty column (never, at this density)
    float f = (float)dmin;
    return f * f;
}

// ---------------------------------------------------------------------------
// Fused kernel: one block per row.
// ---------------------------------------------------------------------------
__global__ void __launch_bounds__(W) k_fused(float* __restrict__ out) {
    __shared__ float sA[W];     // g2 for feature S   (-> dta)
    __shared__ float sB[W];     // g2 for feature S'  (-> dtb)
    __shared__ float wNum[16];
    __shared__ float wDen[16];
    __shared__ bool  isLast;

    const int r = blockIdx.x;
    const int c = threadIdx.x;
    const int q = r >> 5;
    const int bit = r & 31;
    const int lane = c & 31;
    const int wid = c >> 5;

    const uint2 pw = d_pack[q * W + c];          // one coalesced 8B load
    const bool onS  = (pw.x >> bit) & 1u;
    const bool onSp = (pw.y >> bit) & 1u;

    sA[c] = vdist2_bits(pw.x, q, bit, &d_pack[c], false);
    sB[c] = vdist2_bits(pw.y, q, bit, &d_pack[c], true);
    __syncthreads();

    // --- exact row min-plus with batched head + early-exit tail ---
    float num = 0.0f;
    float den = 0.0f;

    if (onSp) {   // dta sampled on S'
        float best = sA[c];
        #pragma unroll
        for (int d = 1; d <= 3; ++d) {
            float dd = (float)(d * d);
            if (c - d >= 0) best = fminf(best, sA[c - d] + dd);
            if (c + d <  W) best = fminf(best, sA[c + d] + dd);
        }
        for (int d = 4; d < W; ++d) {
            float dd = (float)(d * d);
            if (dd >= best) break;
            if (c - d >= 0) best = fminf(best, sA[c - d] + dd);
            if (c + d <  W) best = fminf(best, sA[c + d] + dd);
        }
        num += sqrtf(best);
        den += 1.0f;
    }
    if (onS) {    // dtb sampled on S
        float best = sB[c];
        #pragma unroll
        for (int d = 1; d <= 3; ++d) {
            float dd = (float)(d * d);
            if (c - d >= 0) best = fminf(best, sB[c - d] + dd);
            if (c + d <  W) best = fminf(best, sB[c + d] + dd);
        }
        for (int d = 4; d < W; ++d) {
            float dd = (float)(d * d);
            if (dd >= best) break;
            if (c - d >= 0) best = fminf(best, sB[c - d] + dd);
            if (c + d <  W) best = fminf(best, sB[c + d] + dd);
        }
        num += sqrtf(best);
        den += 1.0f;
    }

    // --- warp shuffle reduction (deterministic) ---
    #pragma unroll
    for (int off = 16; off > 0; off >>= 1) {
        num += __shfl_down_sync(0xFFFFFFFFu, num, off);
        den += __shfl_down_sync(0xFFFFFFFFu, den, off);
    }
    if (lane == 0) { wNum[wid] = num; wDen[wid] = den; }
    __syncthreads();

    if (wid == 0) {
        float n = (lane < 16) ? wNum[lane] : 0.0f;
        float d = (lane < 16) ? wDen[lane] : 0.0f;
        #pragma unroll
        for (int off = 8; off > 0; off >>= 1) {
            n += __shfl_down_sync(0xFFFFFFFFu, n, off);
            d += __shfl_down_sync(0xFFFFFFFFu, d, off);
        }
        if (lane == 0) {
            d_rowNum[r] = n;
            d_rowDen[r] = d;
            __threadfence();
            unsigned int old = atomicInc(&d_cnt, H - 1);  // wraps -> self-reset
            isLast = (old == H - 1);
        }
    }
    __syncthreads();

    // --- last block folds the 512 row partials ---
    if (isLast) {
        float n = d_rowNum[c];
        float d = d_rowDen[c];
        #pragma unroll
        for (int off = 16; off > 0; off >>= 1) {
            n += __shfl_down_sync(0xFFFFFFFFu, n, off);
            d += __shfl_down_sync(0xFFFFFFFFu, d, off);
        }
        if (lane == 0) { wNum[wid] = n; wDen[wid] = d; }
        __syncthreads();
        if (wid == 0) {
            float nn = (lane < 16) ? wNum[lane] : 0.0f;
            float dd = (lane < 16) ? wDen[lane] : 0.0f;
            #pragma unroll
            for (int off = 8; off > 0; off >>= 1) {
                nn += __shfl_down_sync(0xFFFFFFFFu, nn, off);
                dd += __shfl_down_sync(0xFFFFFFFFu, dd, off);
            }
            if (lane == 0) out[0] = nn / dd;
        }
    }
}

extern "C" void kernel_launch(void* const* d_in, const int* in_sizes, int n_in,
                              void* d_out, int out_size) {
    const float* pred = (const float*)d_in[0];
    const float* gt   = (const float*)d_in[1];
    float* out = (float*)d_out;

    dim3 blk(32, 32);
    dim3 grd(W / 32, H / 32);
    k_pack<<<grd, blk>>>(pred, gt);
    k_fused<<<H, W>>>(out);
}